// round 5
// baseline (speedup 1.0000x reference)
#include <cuda_runtime.h>
#include <math.h>

#define KSEL 16
#define TPB 256
#define GRID 296          // 2 blocks per SM on 148-SM GB300
#define NCAND (GRID * KSEL)

// Scratch for per-block top-16 candidates (no device allocation allowed).
__device__ float g_cval[NCAND];
__device__ int   g_cidx[NCAND];

// ---------------------------------------------------------------------------
// Kernel 1: stream 8M points, exact per-block top-16 of squared distance.
// ---------------------------------------------------------------------------
__global__ void __launch_bounds__(TPB, 2)
locse_topk_pass(const float* __restrict__ P, const int* __restrict__ iptr, int N)
{
    __shared__ float sval[KSEL][TPB];
    __shared__ int   sidx[KSEL][TPB];
    __shared__ float s_wv[TPB / 32];
    __shared__ int   s_wi[TPB / 32];
    __shared__ float s_bv;
    __shared__ int   s_bi;

    const int tid = threadIdx.x;
    const int i   = *iptr;
    const float pix = __ldg(P + 6 * i + 0);
    const float piy = __ldg(P + 6 * i + 1);
    const float piz = __ldg(P + 6 * i + 2);

#pragma unroll
    for (int k = 0; k < KSEL; k++) { sval[k][tid] = -1.0f; sidx[k][tid] = -1; }

    float thrMin = -1.0f;   // current 16th-largest in this thread's list

    auto try_insert = [&](float d2, int pid) {
        if (d2 > thrMin) {
            // find first slot holding the current min (rare path)
            int slot = 0;
#pragma unroll
            for (int k = KSEL - 1; k >= 0; k--)
                if (sval[k][tid] == thrMin) slot = k;
            sval[slot][tid] = d2;
            sidx[slot][tid] = pid;
            float m = sval[0][tid];
#pragma unroll
            for (int k = 1; k < KSEL; k++) m = fminf(m, sval[k][tid]);
            thrMin = m;
        }
    };

    const float4* __restrict__ P4 = (const float4*)P;
    const int stride = GRID * TPB * 4;
    for (int p = (blockIdx.x * TPB + tid) * 4; p < N; p += stride) {
        const int q = (p >> 1) * 3;          // float4 index of floats [6p ...]
        float4 a0 = P4[q + 0];
        float4 a1 = P4[q + 1];
        float4 a2 = P4[q + 2];
        float4 a3 = P4[q + 3];
        float4 a4 = P4[q + 4];
        float4 a5 = P4[q + 5];

        // point p   : (a0.x, a0.y, a0.z)
        // point p+1 : (a1.z, a1.w, a2.x)
        // point p+2 : (a3.x, a3.y, a3.z)
        // point p+3 : (a4.z, a4.w, a5.x)
        {
            float dx = a0.x - pix, dy = a0.y - piy, dz = a0.z - piz;
            float d2 = dx * dx + dy * dy + dz * dz;
            try_insert(d2, p);
        }
        {
            float dx = a1.z - pix, dy = a1.w - piy, dz = a2.x - piz;
            float d2 = dx * dx + dy * dy + dz * dz;
            try_insert(d2, p + 1);
        }
        {
            float dx = a3.x - pix, dy = a3.y - piy, dz = a3.z - piz;
            float d2 = dx * dx + dy * dy + dz * dz;
            try_insert(d2, p + 2);
        }
        {
            float dx = a4.z - pix, dy = a4.w - piy, dz = a5.x - piz;
            float d2 = dx * dx + dy * dy + dz * dz;
            try_insert(d2, p + 3);
        }
    }
    __syncthreads();

    // Block-level top-16 via 16 max-extraction rounds (desc value, asc index).
    for (int sel = 0; sel < KSEL; sel++) {
        float bv = -2.0f;
        int   bi = 0x7fffffff;
#pragma unroll
        for (int k = 0; k < KSEL; k++) {
            float v = sval[k][tid];
            int  ix = sidx[k][tid];
            if (v > bv || (v == bv && ix < bi)) { bv = v; bi = ix; }
        }
#pragma unroll
        for (int off = 16; off; off >>= 1) {
            float ov = __shfl_down_sync(0xffffffffu, bv, off);
            int   oi = __shfl_down_sync(0xffffffffu, bi, off);
            if (ov > bv || (ov == bv && oi < bi)) { bv = ov; bi = oi; }
        }
        if ((tid & 31) == 0) { s_wv[tid >> 5] = bv; s_wi[tid >> 5] = bi; }
        __syncthreads();
        if (tid == 0) {
            float v = s_wv[0];
            int  ix = s_wi[0];
            for (int w = 1; w < TPB / 32; w++) {
                if (s_wv[w] > v || (s_wv[w] == v && s_wi[w] < ix)) { v = s_wv[w]; ix = s_wi[w]; }
            }
            s_bv = v; s_bi = ix;
            g_cval[blockIdx.x * KSEL + sel] = v;
            g_cidx[blockIdx.x * KSEL + sel] = ix;
        }
        __syncthreads();
        const float cvv = s_bv;
        const int   cii = s_bi;
#pragma unroll
        for (int k = 0; k < KSEL; k++)
            if (sidx[k][tid] == cii && sval[k][tid] == cvv) sval[k][tid] = -1.0f;
        __syncthreads();
    }
}

// ---------------------------------------------------------------------------
// Kernel 2: merge candidates to global top-16, gather rows, small GEMM, write.
// Output row k: [nloc(3), R(3)] where R = feat @ W.T + b,
// feat = [pi(3), nloc(3), pi-nloc(3), dist(1)].
// ---------------------------------------------------------------------------
__global__ void __launch_bounds__(TPB)
locse_merge(const float* __restrict__ P, const float* __restrict__ W,
            const float* __restrict__ bvec, const int* __restrict__ iptr,
            float* __restrict__ out)
{
    __shared__ float cv[NCAND];
    __shared__ int   ci[NCAND];
    __shared__ float selv[KSEL];
    __shared__ int   seli[KSEL];
    __shared__ float s_wv[TPB / 32];
    __shared__ int   s_wi[TPB / 32];
    __shared__ float s_bv;
    __shared__ int   s_bi;

    const int tid = threadIdx.x;
    for (int j = tid; j < NCAND; j += TPB) { cv[j] = g_cval[j]; ci[j] = g_cidx[j]; }
    __syncthreads();

    for (int sel = 0; sel < KSEL; sel++) {
        float bv = -2.0f;
        int   bi = 0x7fffffff;
        for (int j = tid; j < NCAND; j += TPB) {
            float v = cv[j];
            int  ix = ci[j];
            if (v > bv || (v == bv && ix < bi)) { bv = v; bi = ix; }
        }
#pragma unroll
        for (int off = 16; off; off >>= 1) {
            float ov = __shfl_down_sync(0xffffffffu, bv, off);
            int   oi = __shfl_down_sync(0xffffffffu, bi, off);
            if (ov > bv || (ov == bv && oi < bi)) { bv = ov; bi = oi; }
        }
        if ((tid & 31) == 0) { s_wv[tid >> 5] = bv; s_wi[tid >> 5] = bi; }
        __syncthreads();
        if (tid == 0) {
            float v = s_wv[0];
            int  ix = s_wi[0];
            for (int w = 1; w < TPB / 32; w++) {
                if (s_wv[w] > v || (s_wv[w] == v && s_wi[w] < ix)) { v = s_wv[w]; ix = s_wi[w]; }
            }
            s_bv = v; s_bi = ix;
            selv[sel] = v; seli[sel] = ix;
        }
        __syncthreads();
        const float cvv = s_bv;
        const int   cii = s_bi;
        for (int j = tid; j < NCAND; j += TPB)
            if (ci[j] == cii && cv[j] == cvv) cv[j] = -1.0f;
        __syncthreads();
    }

    if (tid < KSEL) {
        const int k  = tid;
        const int ix = seli[k];
        const int i  = *iptr;
        const float pix = P[6 * i + 0];
        const float piy = P[6 * i + 1];
        const float piz = P[6 * i + 2];
        const float nx = P[6 * ix + 0];
        const float ny = P[6 * ix + 1];
        const float nz = P[6 * ix + 2];
        const float dx = pix - nx, dy = piy - ny, dz = piz - nz;
        const float dist = sqrtf(dx * dx + dy * dy + dz * dz);

        float feat[10] = { pix, piy, piz, nx, ny, nz, dx, dy, dz, dist };

        out[k * 6 + 0] = nx;
        out[k * 6 + 1] = ny;
        out[k * 6 + 2] = nz;
#pragma unroll
        for (int j = 0; j < 3; j++) {
            float r = bvec[j];
#pragma unroll
            for (int f = 0; f < 10; f++) r += feat[f] * W[j * 10 + f];
            out[k * 6 + 3 + j] = r;
        }
    }
}

// ---------------------------------------------------------------------------
extern "C" void kernel_launch(void* const* d_in, const int* in_sizes, int n_in,
                              void* d_out, int out_size)
{
    const float* P  = (const float*)d_in[0];
    const float* W  = (const float*)d_in[1];
    const float* bv = (const float*)d_in[2];
    const int*   ip = (const int*)d_in[3];
    float* out = (float*)d_out;

    const int N = in_sizes[0] / 6;   // number of points (8,000,000)

    locse_topk_pass<<<GRID, TPB>>>(P, ip, N);
    locse_merge<<<1, TPB>>>(P, W, bv, ip, out);
}

// round 6
// speedup vs baseline: 1.5775x; 1.5775x over previous
#include <cuda_runtime.h>
#include <math.h>

#define KSEL 16
#define TPB 256
#define GRID_PASS 1184        // 8 blocks/SM on 148-SM GB300
#define SAMPLE_BLOCKS 512
#define SAMPLE_TPB 128
#define NSAMPLES (SAMPLE_BLOCKS * SAMPLE_TPB)   // 65536
#define THR_RANK 24           // threshold = 24th largest of block maxima
#define CAP 8192              // candidate buffer capacity (expected ~3000)
#define MAXPER (CAP / TPB)    // 32 candidates per merge thread

#define NEG_BIG (-1.0e30f)

// Device scratch (no allocations allowed).
__device__ float g_bmax[SAMPLE_BLOCKS];
__device__ float g_thr;
__device__ int   g_cnt;
__device__ float g_cv[CAP];
__device__ int   g_ci[CAP];

// ---------------------------------------------------------------------------
// Kernel A: sample 65536 points, per-block max of squared distance.
// ---------------------------------------------------------------------------
__global__ void __launch_bounds__(SAMPLE_TPB)
locse_sample(const float* __restrict__ P, const int* __restrict__ iptr,
             int N, int stride)
{
    const int s = blockIdx.x * SAMPLE_TPB + threadIdx.x;
    long long pt = (long long)s * stride;
    if (pt >= N) pt = N - 1;

    const int i = *iptr;
    const float pix = __ldg(P + 6 * i + 0);
    const float piy = __ldg(P + 6 * i + 1);
    const float piz = __ldg(P + 6 * i + 2);

    const float dx = __ldg(P + 6 * pt + 0) - pix;
    const float dy = __ldg(P + 6 * pt + 1) - piy;
    const float dz = __ldg(P + 6 * pt + 2) - piz;
    float v = dx * dx + dy * dy + dz * dz;

#pragma unroll
    for (int off = 16; off; off >>= 1)
        v = fmaxf(v, __shfl_xor_sync(0xffffffffu, v, off));

    __shared__ float sw[SAMPLE_TPB / 32];
    if ((threadIdx.x & 31) == 0) sw[threadIdx.x >> 5] = v;
    __syncthreads();
    if (threadIdx.x == 0) {
        float m = sw[0];
#pragma unroll
        for (int w = 1; w < SAMPLE_TPB / 32; w++) m = fmaxf(m, sw[w]);
        g_bmax[blockIdx.x] = m;
    }
}

// ---------------------------------------------------------------------------
// Kernel B: threshold = THR_RANK-th largest of the 512 block maxima.
// Also resets the candidate counter.
// ---------------------------------------------------------------------------
__global__ void __launch_bounds__(SAMPLE_BLOCKS)
locse_threshold()
{
    __shared__ float s[SAMPLE_BLOCKS];
    __shared__ float swv[SAMPLE_BLOCKS / 32];
    __shared__ float s_win;

    const int tid = threadIdx.x;
    s[tid] = g_bmax[tid];
    __syncthreads();

    float thr = NEG_BIG;
    for (int r = 0; r < THR_RANK; r++) {
        float v = s[tid];
#pragma unroll
        for (int off = 16; off; off >>= 1)
            v = fmaxf(v, __shfl_xor_sync(0xffffffffu, v, off));
        if ((tid & 31) == 0) swv[tid >> 5] = v;
        __syncthreads();
        if (tid == 0) {
            float m = swv[0];
#pragma unroll
            for (int w = 1; w < SAMPLE_BLOCKS / 32; w++) m = fmaxf(m, swv[w]);
            s_win = m;
        }
        __syncthreads();
        thr = s_win;
        if (s[tid] == thr) s[tid] = NEG_BIG;   // ties all removed -> safe (lower thr)
        __syncthreads();
    }

    if (tid == 0) { g_thr = thr; g_cnt = 0; }
}

// ---------------------------------------------------------------------------
// Kernel C: stream all 8M points; push d2 > thr candidates (expected ~3000).
// ---------------------------------------------------------------------------
__global__ void __launch_bounds__(TPB)
locse_pass(const float* __restrict__ P, const int* __restrict__ iptr, int N)
{
    const int tid = threadIdx.x;
    const int i   = *iptr;
    const float pix = __ldg(P + 6 * i + 0);
    const float piy = __ldg(P + 6 * i + 1);
    const float piz = __ldg(P + 6 * i + 2);
    const float thr = g_thr;

    const float4* __restrict__ P4 = (const float4*)P;
    const int stride = gridDim.x * TPB * 4;

    for (int p = (blockIdx.x * TPB + tid) * 4; p < N; p += stride) {
        if (p + 3 < N) {
            const int q = (p >> 1) * 3;   // float4 index of float [6p]
            float4 a0 = P4[q + 0];
            float4 a1 = P4[q + 1];
            float4 a2 = P4[q + 2];
            float4 a3 = P4[q + 3];
            float4 a4 = P4[q + 4];
            float4 a5 = P4[q + 5];

            float d2a, d2b, d2c, d2d;
            {
                float dx = a0.x - pix, dy = a0.y - piy, dz = a0.z - piz;
                d2a = dx * dx + dy * dy + dz * dz;
            }
            {
                float dx = a1.z - pix, dy = a1.w - piy, dz = a2.x - piz;
                d2b = dx * dx + dy * dy + dz * dz;
            }
            {
                float dx = a3.x - pix, dy = a3.y - piy, dz = a3.z - piz;
                d2c = dx * dx + dy * dy + dz * dz;
            }
            {
                float dx = a4.z - pix, dy = a4.w - piy, dz = a5.x - piz;
                d2d = dx * dx + dy * dy + dz * dz;
            }
            if (d2a > thr) { int pos = atomicAdd(&g_cnt, 1); if (pos < CAP) { g_cv[pos] = d2a; g_ci[pos] = p; } }
            if (d2b > thr) { int pos = atomicAdd(&g_cnt, 1); if (pos < CAP) { g_cv[pos] = d2b; g_ci[pos] = p + 1; } }
            if (d2c > thr) { int pos = atomicAdd(&g_cnt, 1); if (pos < CAP) { g_cv[pos] = d2c; g_ci[pos] = p + 2; } }
            if (d2d > thr) { int pos = atomicAdd(&g_cnt, 1); if (pos < CAP) { g_cv[pos] = d2d; g_ci[pos] = p + 3; } }
        } else {
            for (int t = p; t < N; t++) {
                float dx = __ldg(P + 6 * t + 0) - pix;
                float dy = __ldg(P + 6 * t + 1) - piy;
                float dz = __ldg(P + 6 * t + 2) - piz;
                float d2 = dx * dx + dy * dy + dz * dz;
                if (d2 > thr) { int pos = atomicAdd(&g_cnt, 1); if (pos < CAP) { g_cv[pos] = d2; g_ci[pos] = t; } }
            }
        }
    }
}

// ---------------------------------------------------------------------------
// Kernel D: top-16 of candidates (desc value, asc index), gather + tiny GEMM.
// Candidates cached in registers; removal by (unique) index.
// ---------------------------------------------------------------------------
__global__ void __launch_bounds__(TPB)
locse_merge(const float* __restrict__ P, const float* __restrict__ W,
            const float* __restrict__ bvec, const int* __restrict__ iptr,
            float* __restrict__ out)
{
    __shared__ float swv[TPB / 32];
    __shared__ int   swi[TPB / 32];
    __shared__ float s_bv;
    __shared__ int   s_bi;
    __shared__ int   seli[KSEL];

    const int tid = threadIdx.x;
    int n = g_cnt;
    if (n > CAP) n = CAP;

    float rv[MAXPER];
    int   ri[MAXPER];
#pragma unroll
    for (int k = 0; k < MAXPER; k++) {
        int j = tid + k * TPB;
        if (j < n) { rv[k] = g_cv[j]; ri[k] = g_ci[j]; }
        else       { rv[k] = NEG_BIG; ri[k] = 0x7fffffff; }
    }

    for (int sel = 0; sel < KSEL; sel++) {
        float bv = NEG_BIG;
        int   bi = 0x7fffffff;
#pragma unroll
        for (int k = 0; k < MAXPER; k++) {
            if (rv[k] > bv || (rv[k] == bv && ri[k] < bi)) { bv = rv[k]; bi = ri[k]; }
        }
#pragma unroll
        for (int off = 16; off; off >>= 1) {
            float ov = __shfl_xor_sync(0xffffffffu, bv, off);
            int   oi = __shfl_xor_sync(0xffffffffu, bi, off);
            if (ov > bv || (ov == bv && oi < bi)) { bv = ov; bi = oi; }
        }
        if ((tid & 31) == 0) { swv[tid >> 5] = bv; swi[tid >> 5] = bi; }
        __syncthreads();
        if (tid == 0) {
            float v = swv[0];
            int  ix = swi[0];
#pragma unroll
            for (int w = 1; w < TPB / 32; w++) {
                if (swv[w] > v || (swv[w] == v && swi[w] < ix)) { v = swv[w]; ix = swi[w]; }
            }
            s_bv = v; s_bi = ix; seli[sel] = ix;
        }
        __syncthreads();
        const int win = s_bi;
#pragma unroll
        for (int k = 0; k < MAXPER; k++)
            if (ri[k] == win) rv[k] = NEG_BIG;   // indices unique
        __syncthreads();
    }

    if (tid < KSEL) {
        const int k  = tid;
        const int ix = seli[k];
        const int i  = *iptr;
        const float pix = P[6 * i + 0];
        const float piy = P[6 * i + 1];
        const float piz = P[6 * i + 2];
        const float nx = P[6 * ix + 0];
        const float ny = P[6 * ix + 1];
        const float nz = P[6 * ix + 2];
        const float dx = pix - nx, dy = piy - ny, dz = piz - nz;
        const float dist = sqrtf(dx * dx + dy * dy + dz * dz);

        float feat[10] = { pix, piy, piz, nx, ny, nz, dx, dy, dz, dist };

        out[k * 6 + 0] = nx;
        out[k * 6 + 1] = ny;
        out[k * 6 + 2] = nz;
#pragma unroll
        for (int j = 0; j < 3; j++) {
            float r = bvec[j];
#pragma unroll
            for (int f = 0; f < 10; f++) r += feat[f] * W[j * 10 + f];
            out[k * 6 + 3 + j] = r;
        }
    }
}

// ---------------------------------------------------------------------------
extern "C" void kernel_launch(void* const* d_in, const int* in_sizes, int n_in,
                              void* d_out, int out_size)
{
    const float* P  = (const float*)d_in[0];
    const float* W  = (const float*)d_in[1];
    const float* bv = (const float*)d_in[2];
    const int*   ip = (const int*)d_in[3];
    float* out = (float*)d_out;

    const int N = in_sizes[0] / 6;     // 8,000,000 points
    int stride = N / NSAMPLES;
    if (stride < 1) stride = 1;

    locse_sample<<<SAMPLE_BLOCKS, SAMPLE_TPB>>>(P, ip, N, stride);
    locse_threshold<<<1, SAMPLE_BLOCKS>>>();
    locse_pass<<<GRID_PASS, TPB>>>(P, ip, N);
    locse_merge<<<1, TPB>>>(P, W, bv, ip, out);
}

// round 7
// speedup vs baseline: 1.6910x; 1.0719x over previous
#include <cuda_runtime.h>
#include <math.h>

#define KSEL 16
#define TPB 256
#define GRID_PASS 1184        // 8 blocks/SM on 148-SM GB300
#define SAMPLE_BLOCKS 512
#define SAMPLE_TPB 128
#define NSAMPLES (SAMPLE_BLOCKS * SAMPLE_TPB)   // 65536
#define THR_RANK 20           // threshold = 20th largest of block maxima (need >=17)
#define CAP 8192              // candidate buffer capacity (expected ~2450)
#define MAXPER (CAP / TPB)    // 32 u64 keys per merge thread

#define NEG_BIG (-1.0e30f)
#define UMAX64(a,b) ((a) > (b) ? (a) : (b))

// Device scratch (no allocations allowed).
__device__ float g_bmax[SAMPLE_BLOCKS];
__device__ float g_thr;
__device__ int   g_cnt;
__device__ int   g_tick;          // zero-initialized; reset by consumer
__device__ float g_cv[CAP];
__device__ int   g_ci[CAP];

// ---------------------------------------------------------------------------
// Kernel A: sample 65536 points, per-block max of d2; LAST block computes the
// rank-THR_RANK threshold over the 512 block maxima (one warp, register rounds).
// ---------------------------------------------------------------------------
__global__ void __launch_bounds__(SAMPLE_TPB)
locse_sample(const float* __restrict__ P, const int* __restrict__ iptr,
             int N, int stride)
{
    const int tid = threadIdx.x;
    const int s = blockIdx.x * SAMPLE_TPB + tid;
    long long pt = (long long)s * stride;
    if (pt >= N) pt = N - 1;

    const int i = *iptr;
    const float pix = __ldg(P + 6 * i + 0);
    const float piy = __ldg(P + 6 * i + 1);
    const float piz = __ldg(P + 6 * i + 2);

    const float dx = __ldg(P + 6 * pt + 0) - pix;
    const float dy = __ldg(P + 6 * pt + 1) - piy;
    const float dz = __ldg(P + 6 * pt + 2) - piz;
    float v = dx * dx + dy * dy + dz * dz;

#pragma unroll
    for (int off = 16; off; off >>= 1)
        v = fmaxf(v, __shfl_xor_sync(0xffffffffu, v, off));

    __shared__ float sw[SAMPLE_TPB / 32];
    __shared__ int s_last;
    if ((tid & 31) == 0) sw[tid >> 5] = v;
    __syncthreads();
    if (tid == 0) {
        float m = sw[0];
#pragma unroll
        for (int w = 1; w < SAMPLE_TPB / 32; w++) m = fmaxf(m, sw[w]);
        g_bmax[blockIdx.x] = m;
        __threadfence();
        s_last = (atomicAdd(&g_tick, 1) == SAMPLE_BLOCKS - 1);
    }
    __syncthreads();

    // Last block: one warp selects the THR_RANK-th largest of 512 maxima.
    if (s_last && tid < 32) {
        float rv[SAMPLE_BLOCKS / 32];          // 16 values per lane
#pragma unroll
        for (int k = 0; k < SAMPLE_BLOCKS / 32; k++)
            rv[k] = g_bmax[tid + k * 32];

        float thr = NEG_BIG;
#pragma unroll 1
        for (int r = 0; r < THR_RANK; r++) {
            float a[8];
#pragma unroll
            for (int k = 0; k < 8; k++) a[k] = fmaxf(rv[k], rv[k + 8]);
#pragma unroll
            for (int sgl = 4; sgl > 0; sgl >>= 1)
#pragma unroll
                for (int k = 0; k < sgl; k++) a[k] = fmaxf(a[k], a[k + sgl]);
            float m = a[0];
#pragma unroll
            for (int off = 16; off; off >>= 1)
                m = fmaxf(m, __shfl_xor_sync(0xffffffffu, m, off));
            thr = m;
#pragma unroll
            for (int k = 0; k < SAMPLE_BLOCKS / 32; k++)
                if (rv[k] == m) rv[k] = NEG_BIG;   // ties all removed -> safe
        }
        if (tid == 0) { g_thr = thr; g_cnt = 0; g_tick = 0; }
    }
}

// ---------------------------------------------------------------------------
// Kernel B: stream all 8M points; push d2 > thr candidates (expected ~2450).
// ---------------------------------------------------------------------------
__global__ void __launch_bounds__(TPB)
locse_pass(const float* __restrict__ P, const int* __restrict__ iptr, int N)
{
    const int tid = threadIdx.x;
    const int i   = *iptr;
    const float pix = __ldg(P + 6 * i + 0);
    const float piy = __ldg(P + 6 * i + 1);
    const float piz = __ldg(P + 6 * i + 2);
    const float thr = g_thr;

    const float4* __restrict__ P4 = (const float4*)P;
    const int stride = gridDim.x * TPB * 4;

    for (int p = (blockIdx.x * TPB + tid) * 4; p < N; p += stride) {
        if (p + 3 < N) {
            const int q = (p >> 1) * 3;   // float4 index of float [6p]
            float4 a0 = P4[q + 0];
            float4 a1 = P4[q + 1];
            float4 a2 = P4[q + 2];
            float4 a3 = P4[q + 3];
            float4 a4 = P4[q + 4];
            float4 a5 = P4[q + 5];

            float d2a, d2b, d2c, d2d;
            {
                float dx = a0.x - pix, dy = a0.y - piy, dz = a0.z - piz;
                d2a = dx * dx + dy * dy + dz * dz;
            }
            {
                float dx = a1.z - pix, dy = a1.w - piy, dz = a2.x - piz;
                d2b = dx * dx + dy * dy + dz * dz;
            }
            {
                float dx = a3.x - pix, dy = a3.y - piy, dz = a3.z - piz;
                d2c = dx * dx + dy * dy + dz * dz;
            }
            {
                float dx = a4.z - pix, dy = a4.w - piy, dz = a5.x - piz;
                d2d = dx * dx + dy * dy + dz * dz;
            }
            if (d2a > thr) { int pos = atomicAdd(&g_cnt, 1); if (pos < CAP) { g_cv[pos] = d2a; g_ci[pos] = p; } }
            if (d2b > thr) { int pos = atomicAdd(&g_cnt, 1); if (pos < CAP) { g_cv[pos] = d2b; g_ci[pos] = p + 1; } }
            if (d2c > thr) { int pos = atomicAdd(&g_cnt, 1); if (pos < CAP) { g_cv[pos] = d2c; g_ci[pos] = p + 2; } }
            if (d2d > thr) { int pos = atomicAdd(&g_cnt, 1); if (pos < CAP) { g_cv[pos] = d2d; g_ci[pos] = p + 3; } }
        } else {
            for (int t = p; t < N; t++) {
                float dx = __ldg(P + 6 * t + 0) - pix;
                float dy = __ldg(P + 6 * t + 1) - piy;
                float dz = __ldg(P + 6 * t + 2) - piz;
                float d2 = dx * dx + dy * dy + dz * dz;
                if (d2 > thr) { int pos = atomicAdd(&g_cnt, 1); if (pos < CAP) { g_cv[pos] = d2; g_ci[pos] = t; } }
            }
        }
    }
}

// ---------------------------------------------------------------------------
// Kernel C: top-16 of candidates via u64 keys (desc value, asc index),
// gather rows + tiny GEMM, write 16x6 output.
// key = (float_bits(d2) << 32) | (0xFFFFFFFF - idx)  -> single 64-bit max.
// ---------------------------------------------------------------------------
__global__ void __launch_bounds__(TPB)
locse_merge(const float* __restrict__ P, const float* __restrict__ W,
            const float* __restrict__ bvec, const int* __restrict__ iptr,
            float* __restrict__ out)
{
    __shared__ unsigned long long swk[TPB / 32];
    __shared__ unsigned long long s_win;
    __shared__ int seli[KSEL];

    const int tid = threadIdx.x;
    int n = g_cnt;
    if (n > CAP) n = CAP;

    unsigned long long key[MAXPER];
#pragma unroll
    for (int k = 0; k < MAXPER; k++) {
        int j = tid + k * TPB;
        if (j < n) {
            unsigned vb = __float_as_uint(g_cv[j]);          // d2 >= 0: bits monotone
            unsigned ib = 0xFFFFFFFFu - (unsigned)g_ci[j];   // smaller idx -> larger key
            key[k] = ((unsigned long long)vb << 32) | ib;
        } else {
            key[k] = 0ull;
        }
    }

#pragma unroll 1
    for (int sel = 0; sel < KSEL; sel++) {
        // Balanced tree max over 32 register keys (depth 5, good ILP).
        unsigned long long a[MAXPER / 2];
#pragma unroll
        for (int k = 0; k < MAXPER / 2; k++) a[k] = UMAX64(key[k], key[k + MAXPER / 2]);
#pragma unroll
        for (int s = MAXPER / 4; s > 0; s >>= 1)
#pragma unroll
            for (int k = 0; k < s; k++) a[k] = UMAX64(a[k], a[k + s]);
        unsigned long long m = a[0];

#pragma unroll
        for (int off = 16; off; off >>= 1) {
            unsigned long long o = __shfl_xor_sync(0xffffffffu, m, off);
            m = UMAX64(m, o);
        }
        if ((tid & 31) == 0) swk[tid >> 5] = m;
        __syncthreads();
        if (tid == 0) {
            unsigned long long w = swk[0];
#pragma unroll
            for (int q = 1; q < TPB / 32; q++) w = UMAX64(w, swk[q]);
            s_win = w;
            seli[sel] = (int)(0xFFFFFFFFu - (unsigned)(w & 0xFFFFFFFFull));
        }
        __syncthreads();
        const unsigned long long win = s_win;
#pragma unroll
        for (int k = 0; k < MAXPER; k++)
            if (key[k] == win) key[k] = 0ull;    // keys unique (unique idx)
        __syncthreads();
    }

    if (tid < KSEL) {
        const int k  = tid;
        const int ix = seli[k];
        const int i  = *iptr;
        const float pix = P[6 * i + 0];
        const float piy = P[6 * i + 1];
        const float piz = P[6 * i + 2];
        const float nx = P[6 * ix + 0];
        const float ny = P[6 * ix + 1];
        const float nz = P[6 * ix + 2];
        const float dx = pix - nx, dy = piy - ny, dz = piz - nz;
        const float dist = sqrtf(dx * dx + dy * dy + dz * dz);

        float feat[10] = { pix, piy, piz, nx, ny, nz, dx, dy, dz, dist };

        out[k * 6 + 0] = nx;
        out[k * 6 + 1] = ny;
        out[k * 6 + 2] = nz;
#pragma unroll
        for (int j = 0; j < 3; j++) {
            float r = bvec[j];
#pragma unroll
            for (int f = 0; f < 10; f++) r += feat[f] * W[j * 10 + f];
            out[k * 6 + 3 + j] = r;
        }
    }
}

// ---------------------------------------------------------------------------
extern "C" void kernel_launch(void* const* d_in, const int* in_sizes, int n_in,
                              void* d_out, int out_size)
{
    const float* P  = (const float*)d_in[0];
    const float* W  = (const float*)d_in[1];
    const float* bv = (const float*)d_in[2];
    const int*   ip = (const int*)d_in[3];
    float* out = (float*)d_out;

    const int N = in_sizes[0] / 6;     // 8,000,000 points
    int stride = N / NSAMPLES;
    if (stride < 1) stride = 1;

    locse_sample<<<SAMPLE_BLOCKS, SAMPLE_TPB>>>(P, ip, N, stride);
    locse_pass<<<GRID_PASS, TPB>>>(P, ip, N);
    locse_merge<<<1, TPB>>>(P, W, bv, ip, out);
}

// round 13
// speedup vs baseline: 1.7306x; 1.0234x over previous
#include <cuda_runtime.h>
#include <math.h>

#define KSEL 16
#define TPB 256
#define GRID_PASS 1184        // 8 blocks/SM on 148-SM GB300
#define SAMPLE_BLOCKS 512
#define SAMPLE_TPB 128
#define THR_RANK 17           // provably safe: true top-16 all strictly > thr
#define CAP 8192              // candidate buffer capacity (expected ~2100)
#define MAXPER (CAP / TPB)    // 32 u64 keys per merge thread

#define NEG_BIG (-1.0e30f)
#define UMAX64(a,b) ((a) > (b) ? (a) : (b))

// Device scratch (no allocations allowed).
__device__ float g_bmax[SAMPLE_BLOCKS];
__device__ float g_thr;
__device__ int   g_cnt;
__device__ int   g_tick;          // zero-initialized; reset by consumer
__device__ unsigned long long g_ck[CAP];   // packed (d2bits<<32)|(~idx)

// ---------------------------------------------------------------------------
// Kernel A: 512 blocks each take the max d2 over a CONTIGUOUS 128-point chunk
// (coalesced); LAST block (atomic ticket) computes the rank-THR_RANK
// threshold over the 512 block maxima in one warp's registers.
// ---------------------------------------------------------------------------
__global__ void __launch_bounds__(SAMPLE_TPB)
locse_sample(const float* __restrict__ P, const int* __restrict__ iptr,
             int N, int chunk_stride)
{
    const int tid = threadIdx.x;
    long long pt = (long long)blockIdx.x * chunk_stride + tid;
    if (pt >= N) pt = N - 1;

    const int i = *iptr;
    const float pix = __ldg(P + 6 * i + 0);
    const float piy = __ldg(P + 6 * i + 1);
    const float piz = __ldg(P + 6 * i + 2);

    const float dx = __ldg(P + 6 * pt + 0) - pix;
    const float dy = __ldg(P + 6 * pt + 1) - piy;
    const float dz = __ldg(P + 6 * pt + 2) - piz;
    float v = dx * dx + dy * dy + dz * dz;

#pragma unroll
    for (int off = 16; off; off >>= 1)
        v = fmaxf(v, __shfl_xor_sync(0xffffffffu, v, off));

    __shared__ float sw[SAMPLE_TPB / 32];
    __shared__ int s_last;
    if ((tid & 31) == 0) sw[tid >> 5] = v;
    __syncthreads();
    if (tid == 0) {
        float m = sw[0];
#pragma unroll
        for (int w = 1; w < SAMPLE_TPB / 32; w++) m = fmaxf(m, sw[w]);
        g_bmax[blockIdx.x] = m;
        __threadfence();
        s_last = (atomicAdd(&g_tick, 1) == SAMPLE_BLOCKS - 1);
    }
    __syncthreads();

    // Last block: one warp selects the THR_RANK-th largest of 512 maxima.
    if (s_last && tid < 32) {
        const volatile float* bm = g_bmax;     // post-fence consumer read
        float rv[SAMPLE_BLOCKS / 32];          // 16 values per lane
#pragma unroll
        for (int k = 0; k < SAMPLE_BLOCKS / 32; k++)
            rv[k] = bm[tid + k * 32];

        float thr = NEG_BIG;
#pragma unroll 1
        for (int r = 0; r < THR_RANK; r++) {
            float a[8];
#pragma unroll
            for (int k = 0; k < 8; k++) a[k] = fmaxf(rv[k], rv[k + 8]);
#pragma unroll
            for (int sgl = 4; sgl > 0; sgl >>= 1)
#pragma unroll
                for (int k = 0; k < sgl; k++) a[k] = fmaxf(a[k], a[k + sgl]);
            float m = a[0];
#pragma unroll
            for (int off = 16; off; off >>= 1)
                m = fmaxf(m, __shfl_xor_sync(0xffffffffu, m, off));
            thr = m;
#pragma unroll
            for (int k = 0; k < SAMPLE_BLOCKS / 32; k++)
                if (rv[k] == m) rv[k] = NEG_BIG;   // ties all removed -> safe
        }
        if (tid == 0) { g_thr = thr; g_cnt = 0; g_tick = 0; }
    }
}

// ---------------------------------------------------------------------------
// Kernel B: stream all 8M points; push packed u64 keys for d2 > thr.
// key = (float_bits(d2) << 32) | (0xFFFFFFFF - idx): one 64-bit max gives
// desc-value / asc-index ordering.
// ---------------------------------------------------------------------------
__global__ void __launch_bounds__(TPB)
locse_pass(const float* __restrict__ P, const int* __restrict__ iptr, int N)
{
    const int tid = threadIdx.x;
    const int i   = *iptr;
    const float pix = __ldg(P + 6 * i + 0);
    const float piy = __ldg(P + 6 * i + 1);
    const float piz = __ldg(P + 6 * i + 2);
    const float thr = g_thr;

    const float4* __restrict__ P4 = (const float4*)P;
    const int stride = gridDim.x * TPB * 4;

    for (int p = (blockIdx.x * TPB + tid) * 4; p < N; p += stride) {
        if (p + 3 < N) {
            const int q = (p >> 1) * 3;   // float4 index of float [6p]
            float4 a0 = P4[q + 0];
            float4 a1 = P4[q + 1];
            float4 a2 = P4[q + 2];
            float4 a3 = P4[q + 3];
            float4 a4 = P4[q + 4];
            float4 a5 = P4[q + 5];

            float d2a, d2b, d2c, d2d;
            {
                float dx = a0.x - pix, dy = a0.y - piy, dz = a0.z - piz;
                d2a = dx * dx + dy * dy + dz * dz;
            }
            {
                float dx = a1.z - pix, dy = a1.w - piy, dz = a2.x - piz;
                d2b = dx * dx + dy * dy + dz * dz;
            }
            {
                float dx = a3.x - pix, dy = a3.y - piy, dz = a3.z - piz;
                d2c = dx * dx + dy * dy + dz * dz;
            }
            {
                float dx = a4.z - pix, dy = a4.w - piy, dz = a5.x - piz;
                d2d = dx * dx + dy * dy + dz * dz;
            }
            if (d2a > thr) {
                int pos = atomicAdd(&g_cnt, 1);
                if (pos < CAP) g_ck[pos] = ((unsigned long long)__float_as_uint(d2a) << 32)
                                           | (0xFFFFFFFFu - (unsigned)p);
            }
            if (d2b > thr) {
                int pos = atomicAdd(&g_cnt, 1);
                if (pos < CAP) g_ck[pos] = ((unsigned long long)__float_as_uint(d2b) << 32)
                                           | (0xFFFFFFFFu - (unsigned)(p + 1));
            }
            if (d2c > thr) {
                int pos = atomicAdd(&g_cnt, 1);
                if (pos < CAP) g_ck[pos] = ((unsigned long long)__float_as_uint(d2c) << 32)
                                           | (0xFFFFFFFFu - (unsigned)(p + 2));
            }
            if (d2d > thr) {
                int pos = atomicAdd(&g_cnt, 1);
                if (pos < CAP) g_ck[pos] = ((unsigned long long)__float_as_uint(d2d) << 32)
                                           | (0xFFFFFFFFu - (unsigned)(p + 3));
            }
        } else {
            for (int t = p; t < N; t++) {
                float dx = __ldg(P + 6 * t + 0) - pix;
                float dy = __ldg(P + 6 * t + 1) - piy;
                float dz = __ldg(P + 6 * t + 2) - piz;
                float d2 = dx * dx + dy * dy + dz * dz;
                if (d2 > thr) {
                    int pos = atomicAdd(&g_cnt, 1);
                    if (pos < CAP) g_ck[pos] = ((unsigned long long)__float_as_uint(d2) << 32)
                                               | (0xFFFFFFFFu - (unsigned)t);
                }
            }
        }
    }
}

// ---------------------------------------------------------------------------
// Kernel C: top-16 of candidate keys, gather rows + tiny GEMM, write 16x6.
// ---------------------------------------------------------------------------
__global__ void __launch_bounds__(TPB)
locse_merge(const float* __restrict__ P, const float* __restrict__ W,
            const float* __restrict__ bvec, const int* __restrict__ iptr,
            float* __restrict__ out)
{
    __shared__ unsigned long long swk[TPB / 32];
    __shared__ unsigned long long s_win;
    __shared__ int seli[KSEL];

    const int tid = threadIdx.x;
    int n = g_cnt;
    if (n > CAP) n = CAP;

    unsigned long long key[MAXPER];
#pragma unroll
    for (int k = 0; k < MAXPER; k++) {
        int j = tid + k * TPB;
        key[k] = (j < n) ? g_ck[j] : 0ull;
    }

#pragma unroll 1
    for (int sel = 0; sel < KSEL; sel++) {
        unsigned long long a[MAXPER / 2];
#pragma unroll
        for (int k = 0; k < MAXPER / 2; k++) a[k] = UMAX64(key[k], key[k + MAXPER / 2]);
#pragma unroll
        for (int s = MAXPER / 4; s > 0; s >>= 1)
#pragma unroll
            for (int k = 0; k < s; k++) a[k] = UMAX64(a[k], a[k + s]);
        unsigned long long m = a[0];

#pragma unroll
        for (int off = 16; off; off >>= 1) {
            unsigned long long o = __shfl_xor_sync(0xffffffffu, m, off);
            m = UMAX64(m, o);
        }
        if ((tid & 31) == 0) swk[tid >> 5] = m;
        __syncthreads();
        if (tid == 0) {
            unsigned long long w = swk[0];
#pragma unroll
            for (int q = 1; q < TPB / 32; q++) w = UMAX64(w, swk[q]);
            s_win = w;
            seli[sel] = (int)(0xFFFFFFFFu - (unsigned)(w & 0xFFFFFFFFull));
        }
        __syncthreads();
        const unsigned long long win = s_win;
#pragma unroll
        for (int k = 0; k < MAXPER; k++)
            if (key[k] == win) key[k] = 0ull;    // keys unique (unique idx)
        __syncthreads();
    }

    if (tid < KSEL) {
        const int k  = tid;
        const int ix = seli[k];
        const int i  = *iptr;
        const float pix = P[6 * i + 0];
        const float piy = P[6 * i + 1];
        const float piz = P[6 * i + 2];
        const float nx = P[6 * ix + 0];
        const float ny = P[6 * ix + 1];
        const float nz = P[6 * ix + 2];
        const float dx = pix - nx, dy = piy - ny, dz = piz - nz;
        const float dist = sqrtf(dx * dx + dy * dy + dz * dz);

        float feat[10] = { pix, piy, piz, nx, ny, nz, dx, dy, dz, dist };

        out[k * 6 + 0] = nx;
        out[k * 6 + 1] = ny;
        out[k * 6 + 2] = nz;
#pragma unroll
        for (int j = 0; j < 3; j++) {
            float r = bvec[j];
#pragma unroll
            for (int f = 0; f < 10; f++) r += feat[f] * W[j * 10 + f];
            out[k * 6 + 3 + j] = r;
        }
    }
}

// ---------------------------------------------------------------------------
extern "C" void kernel_launch(void* const* d_in, const int* in_sizes, int n_in,
                              void* d_out, int out_size)
{
    const float* P  = (const float*)d_in[0];
    const float* W  = (const float*)d_in[1];
    const float* bv = (const float*)d_in[2];
    const int*   ip = (const int*)d_in[3];
    float* out = (float*)d_out;

    const int N = in_sizes[0] / 6;     // 8,000,000 points
    int chunk_stride = N / SAMPLE_BLOCKS;
    if (chunk_stride < SAMPLE_TPB) chunk_stride = SAMPLE_TPB;

    locse_sample<<<SAMPLE_BLOCKS, SAMPLE_TPB>>>(P, ip, N, chunk_stride);
    locse_pass<<<GRID_PASS, TPB>>>(P, ip, N);
    locse_merge<<<1, TPB>>>(P, W, bv, ip, out);
}